// round 15
// baseline (speedup 1.0000x reference)
#include <cuda_runtime.h>
#include <cuda_bf16.h>
#include <math.h>
#include <stdint.h>

// ---------------- problem constants ----------------
#define LAYERS 4
#define D 768
#define H 12
#define HD 64
#define V 50257
#define B 2
#define T 1024
#define M (B*T)
#define D3 (3*D)
#define D4 (4*D)
#define EPS 1e-5f

#define FLAG_GELU  1
#define FLAG_ACCUM 2

// ---------------- scratch ----------------
__device__ float g_x   [(size_t)M * D];
__device__ float g_qkv [(size_t)M * D3];   // also split-K partial buffer (2*M*D floats)
__device__ __nv_bfloat16 g_ahi[(size_t)M * D4];
__device__ __nv_bfloat16 g_alo[(size_t)M * D4];
__device__ __nv_bfloat16 g_bhi[(size_t)M * D4];
__device__ __nv_bfloat16 g_blo[(size_t)M * D4];
__device__ __nv_bfloat16 g_whi[(size_t)V * D];
__device__ __nv_bfloat16 g_wlo[(size_t)V * D];

__device__ __forceinline__ uint32_t smem_u32(const void* p) {
    uint32_t a;
    asm("{ .reg .u64 t; cvta.to.shared.u64 t, %1; cvt.u32.u64 %0, t; }" : "=r"(a) : "l"(p));
    return a;
}
__device__ __forceinline__ void split_store(float v, __nv_bfloat16* hi, __nv_bfloat16* lo, size_t idx) {
    __nv_bfloat16 h = __float2bfloat16(v);
    hi[idx] = h;
    lo[idx] = __float2bfloat16(v - __bfloat162float(h));
}
#define CP_COMMIT() asm volatile("cp.async.commit_group;" ::: "memory")
#define CP_WAIT(n)  asm volatile("cp.async.wait_group %0;" :: "n"(n) : "memory")

// ---------------- embedding ----------------
__global__ void embed_kernel(const int* __restrict__ ids,
                             const float* __restrict__ wte,
                             const float* __restrict__ wpe)
{
    int row = blockIdx.x;
    int t   = row % T;
    int id  = ids[row];
    const float* we = wte + (size_t)id * D;
    const float* pe = wpe + (size_t)t  * D;
    float* out = g_x + (size_t)row * D;
    for (int i = threadIdx.x; i < D; i += blockDim.x)
        out[i] = we[i] + pe[i];
}

// ---------------- layernorm -> bf16 hi/lo (single-pass) ----------------
__device__ __forceinline__ void ln_core(float v0, float v1, float v2,
                                        int tid, int lane, int wid,
                                        const float* __restrict__ g,
                                        const float* __restrict__ b,
                                        __nv_bfloat16* __restrict__ ohi,
                                        __nv_bfloat16* __restrict__ olo,
                                        size_t base)
{
    float s  = v0 + v1 + v2;
    float s2 = v0 * v0 + v1 * v1 + v2 * v2;
    #pragma unroll
    for (int o = 16; o; o >>= 1) {
        s  += __shfl_xor_sync(0xFFFFFFFFu, s,  o);
        s2 += __shfl_xor_sync(0xFFFFFFFFu, s2, o);
    }
    __shared__ float ws[8], ws2[8];
    if (lane == 0) { ws[wid] = s; ws2[wid] = s2; }
    __syncthreads();
    s = 0.f; s2 = 0.f;
    #pragma unroll
    for (int i = 0; i < 8; i++) { s += ws[i]; s2 += ws2[i]; }
    float mu   = s * (1.f / (float)D);
    float var  = s2 * (1.f / (float)D) - mu * mu;
    float rstd = rsqrtf(var + EPS);

    split_store(g[tid]       * (v0 - mu) * rstd + b[tid],       ohi, olo, base + tid);
    split_store(g[tid + 256] * (v1 - mu) * rstd + b[tid + 256], ohi, olo, base + tid + 256);
    split_store(g[tid + 512] * (v2 - mu) * rstd + b[tid + 512], ohi, olo, base + tid + 512);
}

__global__ void ln_split_kernel(const float* __restrict__ x,
                                const float* __restrict__ g,
                                const float* __restrict__ b,
                                __nv_bfloat16* __restrict__ ohi,
                                __nv_bfloat16* __restrict__ olo)
{
    int row = blockIdx.x, tid = threadIdx.x;
    int lane = tid & 31, wid = tid >> 5;
    const float* xr = x + (size_t)row * D;
    float v0 = xr[tid], v1 = xr[tid + 256], v2 = xr[tid + 512];
    ln_core(v0, v1, v2, tid, lane, wid, g, b, ohi, olo, (size_t)row * D);
}

// ---------------- fused: x += p0+p1+bias, then LN -> bf16 hi/lo ----------------
__global__ void add_ln_split_kernel(float* __restrict__ x, const float* __restrict__ p,
                                    const float* __restrict__ bias,
                                    const float* __restrict__ g,
                                    const float* __restrict__ b,
                                    __nv_bfloat16* __restrict__ ohi,
                                    __nv_bfloat16* __restrict__ olo)
{
    int row = blockIdx.x, tid = threadIdx.x;
    int lane = tid & 31, wid = tid >> 5;
    size_t base = (size_t)row * D;
    const float* p1 = p + (size_t)M * D;
    float v0 = x[base + tid]       + p[base + tid]       + p1[base + tid]       + bias[tid];
    float v1 = x[base + tid + 256] + p[base + tid + 256] + p1[base + tid + 256] + bias[tid + 256];
    float v2 = x[base + tid + 512] + p[base + tid + 512] + p1[base + tid + 512] + bias[tid + 512];
    x[base + tid]       = v0;
    x[base + tid + 256] = v1;
    x[base + tid + 512] = v2;
    ln_core(v0, v1, v2, tid, lane, wid, g, b, ohi, olo, base);
}

// ---------------- fp32 -> bf16 hi/lo split (wte) ----------------
__global__ void split_kernel(const float* __restrict__ X,
                             __nv_bfloat16* __restrict__ hi,
                             __nv_bfloat16* __restrict__ lo, int n4)
{
    int i = blockIdx.x * blockDim.x + threadIdx.x;
    if (i >= n4) return;
    float4 v = ((const float4*)X)[i];
    float f[4] = {v.x, v.y, v.z, v.w};
    __nv_bfloat16 h[4], l[4];
    #pragma unroll
    for (int j = 0; j < 4; j++) {
        h[j] = __float2bfloat16(f[j]);
        l[j] = __float2bfloat16(f[j] - __bfloat162float(h[j]));
    }
    *(uint2*)(hi + 4 * (size_t)i) = *(uint2*)h;
    *(uint2*)(lo + 4 * (size_t)i) = *(uint2*)l;
}

// ---------------- W[K,N] -> hi/lo[N,K] transpose + split ----------------
__global__ void wsplit_t_kernel(const float* __restrict__ W,
                                __nv_bfloat16* __restrict__ hi,
                                __nv_bfloat16* __restrict__ lo, int K, int N)
{
    __shared__ float tb[32][33];
    int n0 = blockIdx.x * 32, k0 = blockIdx.y * 32;
    int tx = threadIdx.x, ty = threadIdx.y;
    #pragma unroll
    for (int i = 0; i < 4; i++)
        tb[ty + i * 8][tx] = W[(size_t)(k0 + ty + i * 8) * N + n0 + tx];
    __syncthreads();
    #pragma unroll
    for (int i = 0; i < 4; i++) {
        int n = n0 + ty + i * 8, k = k0 + tx;
        float v = tb[tx][ty + i * 8];
        __nv_bfloat16 h = __float2bfloat16(v);
        hi[(size_t)n * K + k] = h;
        lo[(size_t)n * K + k] = __float2bfloat16(v - __bfloat162float(h));
    }
}

// ---------------- mma helpers ----------------
__device__ __forceinline__ void ldsm4(uint32_t addr, uint32_t (&r)[4]) {
    asm volatile("ldmatrix.sync.aligned.m8n8.x4.shared.b16 {%0,%1,%2,%3}, [%4];"
        : "=r"(r[0]), "=r"(r[1]), "=r"(r[2]), "=r"(r[3]) : "r"(addr));
}

template<int MI, int NJ>
__device__ __forceinline__ void mma_pass(float (&acc)[MI][NJ][4],
                                         uint32_t (&a)[MI][4],
                                         uint32_t (&b)[NJ/2][4])
{
    #pragma unroll
    for (int mi = 0; mi < MI; mi++) {
        #pragma unroll
        for (int nj = 0; nj < NJ; nj++) {
            int q = nj >> 1, odd = nj & 1;
            uint32_t b0 = odd ? b[q][1] : b[q][0];
            uint32_t b1 = odd ? b[q][3] : b[q][2];
            asm volatile(
                "mma.sync.aligned.m16n8k16.row.col.f32.bf16.bf16.f32 "
                "{%0,%1,%2,%3}, {%4,%5,%6,%7}, {%8,%9}, {%0,%1,%2,%3};"
                : "+f"(acc[mi][nj][0]), "+f"(acc[mi][nj][1]),
                  "+f"(acc[mi][nj][2]), "+f"(acc[mi][nj][3])
                : "r"(a[mi][0]), "r"(a[mi][1]), "r"(a[mi][2]), "r"(a[mi][3]),
                  "r"(b0), "r"(b1));
        }
    }
}

// ---------------- GEMM (FROZEN R9 mainloop) ----------------
template<int BM, int BN, int WGM, int WGN, int STG, bool GUARD>
__global__ void __launch_bounds__(256, 2)
gemm3x(const __nv_bfloat16* __restrict__ Ahi, const __nv_bfloat16* __restrict__ Alo,
       const __nv_bfloat16* __restrict__ Bhi, const __nv_bfloat16* __restrict__ Blo,
       const float* __restrict__ bias, float* __restrict__ Cf,
       __nv_bfloat16* __restrict__ Chi, __nv_bfloat16* __restrict__ Clo,
       int N, int K, int ldk, int nbase, int flags)
{
    constexpr int WTM = BM / WGM, WTN = BN / WGN;
    constexpr int MI = WTM / 16, NJ = WTN / 8;
    constexpr int ATILE = BM * 64, BTILE = BN * 64;
    constexpr int STAGE = 2 * (ATILE + BTILE);
    constexpr int ACH = BM * 8, BCH = BN * 8;
    constexpr int PER = (ACH + BCH) / 256;

    {
        int zo = blockIdx.z * K;
        Ahi += zo; Alo += zo; Bhi += zo; Blo += zo;
        Cf  += (size_t)blockIdx.z * ((size_t)M * N);
    }

    extern __shared__ char smem[];
    const uint32_t sb = smem_u32(smem);
    const int tid = threadIdx.x, lane = tid & 31, wid = tid >> 5;
    const int wm = wid % WGM, wn = wid / WGM;
    const int m0 = blockIdx.x * BM, n0 = nbase + blockIdx.y * BN;
    const int KT = K / 32;

    float acc[MI][NJ][4] = {};

    auto issue = [&](int t, int s) {
        int kb = t * 32;
        uint32_t sbase = sb + s * STAGE;
        #pragma unroll
        for (int j = 0; j < PER; j++) {
            int id = tid + 256 * j;
            if (id < ACH) {
                int half = (id >= ACH / 2) ? 1 : 0;
                int r  = (id - half * (ACH / 2)) >> 2;
                int ch = id & 3;
                uint32_t dst = sbase + half * ATILE + r * 64 + ((ch ^ ((r >> 1) & 3)) << 4);
                const void* src = (half ? Alo : Ahi) + (size_t)(m0 + r) * ldk + kb + ch * 8;
                asm volatile("cp.async.cg.shared.global [%0], [%1], 16;" :: "r"(dst), "l"(src));
            } else {
                int id2 = id - ACH;
                int half = (id2 >= BCH / 2) ? 1 : 0;
                int r  = (id2 - half * (BCH / 2)) >> 2;
                int ch = id2 & 3;
                int bn = n0 + r;
                uint32_t dst = sbase + 2 * ATILE + half * BTILE + r * 64 + ((ch ^ ((r >> 1) & 3)) << 4);
                if (GUARD) {
                    const void* src = (half ? Blo : Bhi) + (size_t)(bn < N ? bn : 0) * ldk + kb + ch * 8;
                    int sz = (bn < N) ? 16 : 0;
                    asm volatile("cp.async.cg.shared.global [%0], [%1], 16, %2;" :: "r"(dst), "l"(src), "r"(sz));
                } else {
                    const void* src = (half ? Blo : Bhi) + (size_t)bn * ldk + kb + ch * 8;
                    asm volatile("cp.async.cg.shared.global [%0], [%1], 16;" :: "r"(dst), "l"(src));
                }
            }
        }
    };

    #pragma unroll
    for (int p = 0; p < STG - 1; p++) {
        if (p < KT) issue(p, p);
        CP_COMMIT();
    }

    const int lrow = lane & 15;
    const int lh   = lane >> 4;
    const int sw   = (lrow >> 1) & 3;

    for (int t = 0; t < KT; t++) {
        CP_WAIT(STG - 2);
        __syncthreads();

        uint32_t base = sb + (t % STG) * STAGE;
        uint32_t aB = base + (wm * WTM + lrow) * 64;
        uint32_t bB = base + 2 * ATILE + (wn * WTN + lrow) * 64;

        #pragma unroll
        for (int kk = 0; kk < 2; kk++) {
            uint32_t co = (uint32_t)(((kk * 2 + lh) ^ sw) << 4);
            uint32_t ah_[MI][4], al_[MI][4], bh_[NJ / 2][4], bl_[NJ / 2][4];
            #pragma unroll
            for (int mi = 0; mi < MI; mi++) {
                ldsm4(aB + mi * 1024 + co, ah_[mi]);
                ldsm4(aB + mi * 1024 + co + ATILE, al_[mi]);
            }
            #pragma unroll
            for (int q = 0; q < NJ / 2; q++) {
                ldsm4(bB + q * 1024 + co, bh_[q]);
                ldsm4(bB + q * 1024 + co + BTILE, bl_[q]);
            }
            mma_pass<MI, NJ>(acc, ah_, bh_);
            mma_pass<MI, NJ>(acc, al_, bh_);
            mma_pass<MI, NJ>(acc, ah_, bl_);
        }

        int tn = t + STG - 1;
        if (tn < KT) issue(tn, tn % STG);
        CP_COMMIT();
    }

    int mrow = m0 + wm * WTM + (lane >> 2);
    int ncol = n0 + wn * WTN + (lane & 3) * 2;
    #pragma unroll
    for (int mi = 0; mi < MI; mi++) {
        int r0 = mrow + mi * 16;
        #pragma unroll
        for (int nj = 0; nj < NJ; nj++) {
            int cb = ncol + nj * 8;
            #pragma unroll
            for (int half = 0; half < 2; half++) {
                int r = r0 + half * 8;
                size_t rowoff = (size_t)r * N;
                #pragma unroll
                for (int e = 0; e < 2; e++) {
                    int n = cb + e;
                    if (n < N) {
                        float v = acc[mi][nj][half * 2 + e];
                        if (bias) v += bias[n];
                        if (flags & FLAG_GELU)
                            v = 0.5f * v * (1.f + erff(v * 0.70710678118654752f));
                        if (Chi) {
                            split_store(v, Chi, Clo, rowoff + n);
                        } else {
                            if (flags & FLAG_ACCUM) v += Cf[rowoff + n];
                            Cf[rowoff + n] = v;
                        }
                    }
                }
            }
        }
    }
}

#define SMEM_BIG   (3 * 2 * (128 * 64 + 128 * 64))
#define SMEM_SMALL (4 * 2 * (64 * 64 + 128 * 64))

// ---------------- attention: 16 q per block, 2-stage KV ring ----------------
#define QT 16
#define ATT_SMEM (QT*64*4 + QT*T*4 + 2*64*256 + 64)   // 102464

__global__ void __launch_bounds__(256, 2)
attention16(const float* __restrict__ qkv,
            __nv_bfloat16* __restrict__ ohi,
            __nv_bfloat16* __restrict__ olo)
{
    extern __shared__ char smem[];
    float* qs   = (float*)smem;                    // QT*64
    float* sc   = qs + QT * 64;                    // QT*T
    char*  kvb  = (char*)(sc + QT * T);            // 2 * 16KB
    float* invs = (float*)(kvb + 2 * 64 * 256);    // QT
    uint32_t kv0 = smem_u32(kvb);

    int qt = blockIdx.x, bh = blockIdx.y;
    int b = bh / H, h = bh % H;
    int q0 = qt * QT;
    int tid = threadIdx.x, lane = tid & 31, wid = tid >> 5;
    const float* base = qkv + (size_t)b * T * D3;

    // q rows, prescaled
    #pragma unroll
    for (int j = 0; j < 4; j++) {
        int i = tid + j * 256;
        int qq = i >> 6, d = i & 63;
        qs[i] = base[(size_t)(q0 + qq) * D3 + h * HD + d] * 0.125f;
    }

    int ntile = (q0 + QT + 63) / 64;

    auto issueKV = [&](int t, int s, int off) {
        #pragma unroll
        for (int j = 0; j < 4; j++) {
            int id = tid + j * 256;
            int r = id >> 4, ch = id & 15;
            uint32_t dst = kv0 + s * 16384 + r * 256 + ((ch ^ (r & 7)) << 4);
            const void* src = base + (size_t)(t * 64 + r) * D3 + off + h * HD + ch * 4;
            asm volatile("cp.async.cg.shared.global [%0], [%1], 16;" :: "r"(dst), "l"(src));
        }
    };

    // ---- phase 1: scores (warp w -> q rows 2w, 2w+1; 2 keys/lane) ----
    issueKV(0, 0, D);
    CP_COMMIT();
    int qp = wid * 2;
    for (int t = 0; t < ntile; t++) {
        CP_WAIT(0);
        __syncthreads();
        if (t + 1 < ntile) { issueKV(t + 1, (t + 1) & 1, D); CP_COMMIT(); }
        char* tbase = kvb + (t & 1) * 16384;
        #pragma unroll
        for (int rr = 0; rr < 2; rr++) {
            int r = lane + rr * 32;
            char* rowp = tbase + r * 256;
            int rsw = r & 7;
            float s0 = 0.f, s1 = 0.f;
            #pragma unroll
            for (int c = 0; c < 16; c++) {
                float4 kv4 = *(const float4*)(rowp + ((c ^ rsw) << 4));
                float4 a  = *(const float4*)(qs + qp * 64 + c * 4);
                float4 bq = *(const float4*)(qs + (qp + 1) * 64 + c * 4);
                s0 = fmaf(a.x,  kv4.x, s0); s0 = fmaf(a.y,  kv4.y, s0);
                s0 = fmaf(a.z,  kv4.z, s0); s0 = fmaf(a.w,  kv4.w, s0);
                s1 = fmaf(bq.x, kv4.x, s1); s1 = fmaf(bq.y, kv4.y, s1);
                s1 = fmaf(bq.z, kv4.z, s1); s1 = fmaf(bq.w, kv4.w, s1);
            }
            sc[qp * T + t * 64 + r] = s0;
            sc[(qp + 1) * T + t * 64 + r] = s1;
        }
    }
    __syncthreads();

    // ---- phase 2: softmax (warp w -> rows 2w, 2w+1) ----
    #pragma unroll
    for (int sub = 0; sub < 2; sub++) {
        int w = wid * 2 + sub;
        int nk = q0 + w + 1;
        float* row = sc + w * T;
        float m = -1e30f;
        for (int k = lane; k < nk; k += 32) m = fmaxf(m, row[k]);
        #pragma unroll
        for (int o = 16; o; o >>= 1) m = fmaxf(m, __shfl_xor_sync(0xFFFFFFFFu, m, o));
        float sum = 0.f;
        for (int k = lane; k < nk; k += 32) {
            float e = __expf(row[k] - m);
            row[k] = e;
            sum += e;
        }
        #pragma unroll
        for (int o = 16; o; o >>= 1) sum += __shfl_xor_sync(0xFFFFFFFFu, sum, o);
        for (int k = nk + lane - ((nk) & 31) + (lane >= (nk & 31) ? 0 : 32); 0; ) break; // (unused)
        for (int k = nk + lane; k < ntile * 64; k += 32) row[k] = 0.f;
        if (lane == 0) invs[w] = 1.f / sum;
    }
    __syncthreads();

    // ---- phase 3: PV (thread -> d, q rows g,g+4,g+8,g+12) ----
    issueKV(0, 0, 2 * D);
    CP_COMMIT();
    int d = tid & 63, g = tid >> 6;
    int c = d >> 2, e4 = (d & 3) * 4;
    float a0 = 0.f, a1 = 0.f, a2 = 0.f, a3 = 0.f;
    for (int t = 0; t < ntile; t++) {
        CP_WAIT(0);
        __syncthreads();
        if (t + 1 < ntile) { issueKV(t + 1, (t + 1) & 1, 2 * D); CP_COMMIT(); }
        const float* p0 = sc + g * T + t * 64;
        const float* p1 = sc + (g + 4) * T + t * 64;
        const float* p2 = sc + (g + 8) * T + t * 64;
        const float* p3 = sc + (g + 12) * T + t * 64;
        char* tb = kvb + (t & 1) * 16384;
        #pragma unroll 8
        for (int r = 0; r < 64; r++) {
            float v = *(const float*)(tb + r * 256 + ((c ^ (r & 7)) << 4) + e4);
            a0 = fmaf(p0[r], v, a0);
            a1 = fmaf(p1[r], v, a1);
            a2 = fmaf(p2[r], v, a2);
            a3 = fmaf(p3[r], v, a3);
        }
    }

    size_t obase = (size_t)(b * T + q0) * D + h * HD + d;
    split_store(a0 * invs[g],      ohi, olo, obase + (size_t)(g)      * D);
    split_store(a1 * invs[g + 4],  ohi, olo, obase + (size_t)(g + 4)  * D);
    split_store(a2 * invs[g + 8],  ohi, olo, obase + (size_t)(g + 8)  * D);
    split_store(a3 * invs[g + 12], ohi, olo, obase + (size_t)(g + 12) * D);
}

// ---------------- host side ----------------
static inline void run_gemm_big(const __nv_bfloat16* Ahi, const __nv_bfloat16* Alo,
                                const __nv_bfloat16* Bhi, const __nv_bfloat16* Blo,
                                const float* bias, float* Cf,
                                __nv_bfloat16* Chi, __nv_bfloat16* Clo,
                                int N, int K, int flags)
{
    dim3 grid(M / 128, N / 128);
    gemm3x<128, 128, 4, 2, 3, false><<<grid, 256, SMEM_BIG>>>(Ahi, Alo, Bhi, Blo, bias, Cf, Chi, Clo, N, K, K, 0, flags);
}
static inline void run_gemm_lmhead(const __nv_bfloat16* Ahi, const __nv_bfloat16* Alo,
                                   const __nv_bfloat16* Bhi, const __nv_bfloat16* Blo,
                                   float* Cf, int N, int K)
{
    int nfull = (N / 128) * 128;
    dim3 grid(M / 128, nfull / 128);
    gemm3x<128, 128, 4, 2, 3, false><<<grid, 256, SMEM_BIG>>>(Ahi, Alo, Bhi, Blo, nullptr, Cf,
                                                              nullptr, nullptr, N, K, K, 0, 0);
    dim3 gridr(M / 128, 1);
    gemm3x<128, 128, 4, 2, 3, true><<<gridr, 256, SMEM_BIG>>>(Ahi, Alo, Bhi, Blo, nullptr, Cf,
                                                              nullptr, nullptr, N, K, K, nfull, 0);
}
// split-K x2 (no reduction — fused add_ln follows)
static inline void run_gemm_splitk(const __nv_bfloat16* Ahi, const __nv_bfloat16* Alo,
                                   const __nv_bfloat16* Bhi, const __nv_bfloat16* Blo,
                                   float* partial, int K)
{
    dim3 grid(M / 64, D / 128, 2);
    gemm3x<64, 128, 2, 4, 4, false><<<grid, 256, SMEM_SMALL>>>(Ahi, Alo, Bhi, Blo, nullptr, partial,
                                                               nullptr, nullptr, D, K / 2, K, 0, 0);
}
static inline void run_split(const float* X, __nv_bfloat16* hi, __nv_bfloat16* lo, size_t n)
{
    int n4 = (int)(n / 4);
    split_kernel<<<(n4 + 255) / 256, 256>>>(X, hi, lo, n4);
}
static inline void run_wsplit(const float* W, __nv_bfloat16* hi, __nv_bfloat16* lo, int K, int N)
{
    dim3 grid(N / 32, K / 32);
    wsplit_t_kernel<<<grid, dim3(32, 8)>>>(W, hi, lo, K, N);
}

extern "C" void kernel_launch(void* const* d_in, const int* in_sizes, int n_in,
                              void* d_out, int out_size)
{
    const int*   ids    = (const int*)  d_in[0];
    const float* wte    = (const float*)d_in[1];
    const float* wpe    = (const float*)d_in[2];
    const float* ln1_g  = (const float*)d_in[3];
    const float* ln1_b  = (const float*)d_in[4];
    const float* attn_w = (const float*)d_in[5];
    const float* attn_b = (const float*)d_in[6];
    const float* proj_w = (const float*)d_in[7];
    const float* proj_b = (const float*)d_in[8];
    const float* ln2_g  = (const float*)d_in[9];
    const float* ln2_b  = (const float*)d_in[10];
    const float* fc_w   = (const float*)d_in[11];
    const float* fc_b   = (const float*)d_in[12];
    const float* out_w  = (const float*)d_in[13];
    const float* out_b  = (const float*)d_in[14];
    const float* lnf_g  = (const float*)d_in[15];
    const float* lnf_b  = (const float*)d_in[16];
    float* logits = (float*)d_out;

    cudaFuncSetAttribute((const void*)gemm3x<128, 128, 4, 2, 3, false>, cudaFuncAttributeMaxDynamicSharedMemorySize, SMEM_BIG);
    cudaFuncSetAttribute((const void*)gemm3x<128, 128, 4, 2, 3, true>,  cudaFuncAttributeMaxDynamicSharedMemorySize, SMEM_BIG);
    cudaFuncSetAttribute((const void*)gemm3x<64, 128, 2, 4, 4, false>,  cudaFuncAttributeMaxDynamicSharedMemorySize, SMEM_SMALL);
    cudaFuncSetAttribute((const void*)attention16, cudaFuncAttributeMaxDynamicSharedMemorySize, ATT_SMEM);

    float *x, *qkv;
    __nv_bfloat16 *ahi, *alo, *bhi, *blo, *whi, *wlo;
    cudaGetSymbolAddress((void**)&x,    g_x);
    cudaGetSymbolAddress((void**)&qkv,  g_qkv);
    cudaGetSymbolAddress((void**)&ahi,  g_ahi);
    cudaGetSymbolAddress((void**)&alo,  g_alo);
    cudaGetSymbolAddress((void**)&bhi,  g_bhi);
    cudaGetSymbolAddress((void**)&blo,  g_blo);
    cudaGetSymbolAddress((void**)&whi,  g_whi);
    cudaGetSymbolAddress((void**)&wlo,  g_wlo);

    embed_kernel<<<M, 256>>>(ids, wte, wpe);

    for (int l = 0; l < LAYERS; l++) {
        const float* aw = attn_w + (size_t)l * D * D3;
        const float* ab = attn_b + (size_t)l * D3;
        const float* pw = proj_w + (size_t)l * D * D;
        const float* pb = proj_b + (size_t)l * D;
        const float* fw = fc_w   + (size_t)l * D * D4;
        const float* fb = fc_b   + (size_t)l * D4;
        const float* ow = out_w  + (size_t)l * D4 * D;
        const float* ob = out_b  + (size_t)l * D;

        // attention block
        if (l == 0)
            ln_split_kernel<<<M, 256>>>(x, ln1_g, ln1_b, ahi, alo);
        run_wsplit(aw, whi, wlo, D, D3);
        run_gemm_big(ahi, alo, whi, wlo, ab, qkv, nullptr, nullptr, D3, D, 0);
        {
            dim3 grid(T / QT, B * H);
            attention16<<<grid, 256, ATT_SMEM>>>(qkv, ahi, alo);
        }
        run_wsplit(pw, whi, wlo, D, D);
        run_gemm_splitk(ahi, alo, whi, wlo, qkv, D);
        add_ln_split_kernel<<<M, 256>>>(x, qkv, pb,
                                        ln2_g + (size_t)l * D, ln2_b + (size_t)l * D, ahi, alo);

        // mlp block
        run_wsplit(fw, whi, wlo, D, D4);
        run_gemm_big(ahi, alo, whi, wlo, fb, nullptr, bhi, blo, D4, D, FLAG_GELU);
        run_wsplit(ow, whi, wlo, D4, D);
        run_gemm_splitk(bhi, blo, whi, wlo, qkv, D4);
        const float* ng = (l + 1 < LAYERS) ? ln1_g + (size_t)(l + 1) * D : lnf_g;
        const float* nb = (l + 1 < LAYERS) ? ln1_b + (size_t)(l + 1) * D : lnf_b;
        add_ln_split_kernel<<<M, 256>>>(x, qkv, ob, ng, nb, ahi, alo);
    }

    // tied lm_head (ahi/alo already hold lnf output)
    run_split(wte, whi, wlo, (size_t)V * D);
    run_gemm_lmhead(ahi, alo, whi, wlo, logits, V, D);
}

// round 16
// speedup vs baseline: 1.0265x; 1.0265x over previous
#include <cuda_runtime.h>
#include <cuda_bf16.h>
#include <math.h>
#include <stdint.h>

// ---------------- problem constants ----------------
#define LAYERS 4
#define D 768
#define H 12
#define HD 64
#define V 50257
#define B 2
#define T 1024
#define M (B*T)
#define D3 (3*D)
#define D4 (4*D)
#define EPS 1e-5f

#define FLAG_GELU  1
#define FLAG_ACCUM 2

// ---------------- scratch ----------------
__device__ float g_x   [(size_t)M * D];
__device__ float g_qkv [(size_t)M * D3];   // also split-K partial buffer (2*M*D floats)
__device__ __nv_bfloat16 g_ahi[(size_t)M * D4];
__device__ __nv_bfloat16 g_alo[(size_t)M * D4];
__device__ __nv_bfloat16 g_bhi[(size_t)M * D4];
__device__ __nv_bfloat16 g_blo[(size_t)M * D4];
__device__ __nv_bfloat16 g_whi[(size_t)V * D];
__device__ __nv_bfloat16 g_wlo[(size_t)V * D];

__device__ __forceinline__ uint32_t smem_u32(const void* p) {
    uint32_t a;
    asm("{ .reg .u64 t; cvta.to.shared.u64 t, %1; cvt.u32.u64 %0, t; }" : "=r"(a) : "l"(p));
    return a;
}
__device__ __forceinline__ void split_store(float v, __nv_bfloat16* hi, __nv_bfloat16* lo, size_t idx) {
    __nv_bfloat16 h = __float2bfloat16(v);
    hi[idx] = h;
    lo[idx] = __float2bfloat16(v - __bfloat162float(h));
}
#define CP_COMMIT() asm volatile("cp.async.commit_group;" ::: "memory")
#define CP_WAIT(n)  asm volatile("cp.async.wait_group %0;" :: "n"(n) : "memory")

// ---------------- embedding ----------------
__global__ void embed_kernel(const int* __restrict__ ids,
                             const float* __restrict__ wte,
                             const float* __restrict__ wpe)
{
    int row = blockIdx.x;
    int t   = row % T;
    int id  = ids[row];
    const float* we = wte + (size_t)id * D;
    const float* pe = wpe + (size_t)t  * D;
    float* out = g_x + (size_t)row * D;
    for (int i = threadIdx.x; i < D; i += blockDim.x)
        out[i] = we[i] + pe[i];
}

// ---------------- layernorm -> bf16 hi/lo (single-pass) ----------------
__device__ __forceinline__ void ln_core(float v0, float v1, float v2,
                                        int tid, int lane, int wid,
                                        const float* __restrict__ g,
                                        const float* __restrict__ b,
                                        __nv_bfloat16* __restrict__ ohi,
                                        __nv_bfloat16* __restrict__ olo,
                                        size_t base)
{
    float s  = v0 + v1 + v2;
    float s2 = v0 * v0 + v1 * v1 + v2 * v2;
    #pragma unroll
    for (int o = 16; o; o >>= 1) {
        s  += __shfl_xor_sync(0xFFFFFFFFu, s,  o);
        s2 += __shfl_xor_sync(0xFFFFFFFFu, s2, o);
    }
    __shared__ float ws[8], ws2[8];
    if (lane == 0) { ws[wid] = s; ws2[wid] = s2; }
    __syncthreads();
    s = 0.f; s2 = 0.f;
    #pragma unroll
    for (int i = 0; i < 8; i++) { s += ws[i]; s2 += ws2[i]; }
    float mu   = s * (1.f / (float)D);
    float var  = s2 * (1.f / (float)D) - mu * mu;
    float rstd = rsqrtf(var + EPS);

    split_store(g[tid]       * (v0 - mu) * rstd + b[tid],       ohi, olo, base + tid);
    split_store(g[tid + 256] * (v1 - mu) * rstd + b[tid + 256], ohi, olo, base + tid + 256);
    split_store(g[tid + 512] * (v2 - mu) * rstd + b[tid + 512], ohi, olo, base + tid + 512);
}

__global__ void ln_split_kernel(const float* __restrict__ x,
                                const float* __restrict__ g,
                                const float* __restrict__ b,
                                __nv_bfloat16* __restrict__ ohi,
                                __nv_bfloat16* __restrict__ olo)
{
    int row = blockIdx.x, tid = threadIdx.x;
    int lane = tid & 31, wid = tid >> 5;
    const float* xr = x + (size_t)row * D;
    float v0 = xr[tid], v1 = xr[tid + 256], v2 = xr[tid + 512];
    ln_core(v0, v1, v2, tid, lane, wid, g, b, ohi, olo, (size_t)row * D);
}

// ---------------- fused: x += p0+p1+bias, then LN -> bf16 hi/lo ----------------
__global__ void add_ln_split_kernel(float* __restrict__ x, const float* __restrict__ p,
                                    const float* __restrict__ bias,
                                    const float* __restrict__ g,
                                    const float* __restrict__ b,
                                    __nv_bfloat16* __restrict__ ohi,
                                    __nv_bfloat16* __restrict__ olo)
{
    int row = blockIdx.x, tid = threadIdx.x;
    int lane = tid & 31, wid = tid >> 5;
    size_t base = (size_t)row * D;
    const float* p1 = p + (size_t)M * D;
    float v0 = x[base + tid]       + p[base + tid]       + p1[base + tid]       + bias[tid];
    float v1 = x[base + tid + 256] + p[base + tid + 256] + p1[base + tid + 256] + bias[tid + 256];
    float v2 = x[base + tid + 512] + p[base + tid + 512] + p1[base + tid + 512] + bias[tid + 512];
    x[base + tid]       = v0;
    x[base + tid + 256] = v1;
    x[base + tid + 512] = v2;
    ln_core(v0, v1, v2, tid, lane, wid, g, b, ohi, olo, base);
}

// ---------------- fp32 -> bf16 hi/lo split (wte) ----------------
__global__ void split_kernel(const float* __restrict__ X,
                             __nv_bfloat16* __restrict__ hi,
                             __nv_bfloat16* __restrict__ lo, int n4)
{
    int i = blockIdx.x * blockDim.x + threadIdx.x;
    if (i >= n4) return;
    float4 v = ((const float4*)X)[i];
    float f[4] = {v.x, v.y, v.z, v.w};
    __nv_bfloat16 h[4], l[4];
    #pragma unroll
    for (int j = 0; j < 4; j++) {
        h[j] = __float2bfloat16(f[j]);
        l[j] = __float2bfloat16(f[j] - __bfloat162float(h[j]));
    }
    *(uint2*)(hi + 4 * (size_t)i) = *(uint2*)h;
    *(uint2*)(lo + 4 * (size_t)i) = *(uint2*)l;
}

// ---------------- W[K,N] -> hi/lo[N,K] transpose + split ----------------
__global__ void wsplit_t_kernel(const float* __restrict__ W,
                                __nv_bfloat16* __restrict__ hi,
                                __nv_bfloat16* __restrict__ lo, int K, int N)
{
    __shared__ float tb[32][33];
    int n0 = blockIdx.x * 32, k0 = blockIdx.y * 32;
    int tx = threadIdx.x, ty = threadIdx.y;
    #pragma unroll
    for (int i = 0; i < 4; i++)
        tb[ty + i * 8][tx] = W[(size_t)(k0 + ty + i * 8) * N + n0 + tx];
    __syncthreads();
    #pragma unroll
    for (int i = 0; i < 4; i++) {
        int n = n0 + ty + i * 8, k = k0 + tx;
        float v = tb[tx][ty + i * 8];
        __nv_bfloat16 h = __float2bfloat16(v);
        hi[(size_t)n * K + k] = h;
        lo[(size_t)n * K + k] = __float2bfloat16(v - __bfloat162float(h));
    }
}

// ---------------- mma helpers ----------------
__device__ __forceinline__ void ldsm4(uint32_t addr, uint32_t (&r)[4]) {
    asm volatile("ldmatrix.sync.aligned.m8n8.x4.shared.b16 {%0,%1,%2,%3}, [%4];"
        : "=r"(r[0]), "=r"(r[1]), "=r"(r[2]), "=r"(r[3]) : "r"(addr));
}

template<int MI, int NJ>
__device__ __forceinline__ void mma_pass(float (&acc)[MI][NJ][4],
                                         uint32_t (&a)[MI][4],
                                         uint32_t (&b)[NJ/2][4])
{
    #pragma unroll
    for (int mi = 0; mi < MI; mi++) {
        #pragma unroll
        for (int nj = 0; nj < NJ; nj++) {
            int q = nj >> 1, odd = nj & 1;
            uint32_t b0 = odd ? b[q][1] : b[q][0];
            uint32_t b1 = odd ? b[q][3] : b[q][2];
            asm volatile(
                "mma.sync.aligned.m16n8k16.row.col.f32.bf16.bf16.f32 "
                "{%0,%1,%2,%3}, {%4,%5,%6,%7}, {%8,%9}, {%0,%1,%2,%3};"
                : "+f"(acc[mi][nj][0]), "+f"(acc[mi][nj][1]),
                  "+f"(acc[mi][nj][2]), "+f"(acc[mi][nj][3])
                : "r"(a[mi][0]), "r"(a[mi][1]), "r"(a[mi][2]), "r"(a[mi][3]),
                  "r"(b0), "r"(b1));
        }
    }
}

// ---------------- GEMM (FROZEN R9 mainloop) ----------------
template<int BM, int BN, int WGM, int WGN, int STG, bool GUARD>
__global__ void __launch_bounds__(256, 2)
gemm3x(const __nv_bfloat16* __restrict__ Ahi, const __nv_bfloat16* __restrict__ Alo,
       const __nv_bfloat16* __restrict__ Bhi, const __nv_bfloat16* __restrict__ Blo,
       const float* __restrict__ bias, float* __restrict__ Cf,
       __nv_bfloat16* __restrict__ Chi, __nv_bfloat16* __restrict__ Clo,
       int N, int K, int ldk, int nbase, int flags)
{
    constexpr int WTM = BM / WGM, WTN = BN / WGN;
    constexpr int MI = WTM / 16, NJ = WTN / 8;
    constexpr int ATILE = BM * 64, BTILE = BN * 64;
    constexpr int STAGE = 2 * (ATILE + BTILE);
    constexpr int ACH = BM * 8, BCH = BN * 8;
    constexpr int PER = (ACH + BCH) / 256;

    {
        int zo = blockIdx.z * K;
        Ahi += zo; Alo += zo; Bhi += zo; Blo += zo;
        Cf  += (size_t)blockIdx.z * ((size_t)M * N);
    }

    extern __shared__ char smem[];
    const uint32_t sb = smem_u32(smem);
    const int tid = threadIdx.x, lane = tid & 31, wid = tid >> 5;
    const int wm = wid % WGM, wn = wid / WGM;
    const int m0 = blockIdx.x * BM, n0 = nbase + blockIdx.y * BN;
    const int KT = K / 32;

    float acc[MI][NJ][4] = {};

    auto issue = [&](int t, int s) {
        int kb = t * 32;
        uint32_t sbase = sb + s * STAGE;
        #pragma unroll
        for (int j = 0; j < PER; j++) {
            int id = tid + 256 * j;
            if (id < ACH) {
                int half = (id >= ACH / 2) ? 1 : 0;
                int r  = (id - half * (ACH / 2)) >> 2;
                int ch = id & 3;
                uint32_t dst = sbase + half * ATILE + r * 64 + ((ch ^ ((r >> 1) & 3)) << 4);
                const void* src = (half ? Alo : Ahi) + (size_t)(m0 + r) * ldk + kb + ch * 8;
                asm volatile("cp.async.cg.shared.global [%0], [%1], 16;" :: "r"(dst), "l"(src));
            } else {
                int id2 = id - ACH;
                int half = (id2 >= BCH / 2) ? 1 : 0;
                int r  = (id2 - half * (BCH / 2)) >> 2;
                int ch = id2 & 3;
                int bn = n0 + r;
                uint32_t dst = sbase + 2 * ATILE + half * BTILE + r * 64 + ((ch ^ ((r >> 1) & 3)) << 4);
                if (GUARD) {
                    const void* src = (half ? Blo : Bhi) + (size_t)(bn < N ? bn : 0) * ldk + kb + ch * 8;
                    int sz = (bn < N) ? 16 : 0;
                    asm volatile("cp.async.cg.shared.global [%0], [%1], 16, %2;" :: "r"(dst), "l"(src), "r"(sz));
                } else {
                    const void* src = (half ? Blo : Bhi) + (size_t)bn * ldk + kb + ch * 8;
                    asm volatile("cp.async.cg.shared.global [%0], [%1], 16;" :: "r"(dst), "l"(src));
                }
            }
        }
    };

    #pragma unroll
    for (int p = 0; p < STG - 1; p++) {
        if (p < KT) issue(p, p);
        CP_COMMIT();
    }

    const int lrow = lane & 15;
    const int lh   = lane >> 4;
    const int sw   = (lrow >> 1) & 3;

    for (int t = 0; t < KT; t++) {
        CP_WAIT(STG - 2);
        __syncthreads();

        uint32_t base = sb + (t % STG) * STAGE;
        uint32_t aB = base + (wm * WTM + lrow) * 64;
        uint32_t bB = base + 2 * ATILE + (wn * WTN + lrow) * 64;

        #pragma unroll
        for (int kk = 0; kk < 2; kk++) {
            uint32_t co = (uint32_t)(((kk * 2 + lh) ^ sw) << 4);
            uint32_t ah_[MI][4], al_[MI][4], bh_[NJ / 2][4], bl_[NJ / 2][4];
            #pragma unroll
            for (int mi = 0; mi < MI; mi++) {
                ldsm4(aB + mi * 1024 + co, ah_[mi]);
                ldsm4(aB + mi * 1024 + co + ATILE, al_[mi]);
            }
            #pragma unroll
            for (int q = 0; q < NJ / 2; q++) {
                ldsm4(bB + q * 1024 + co, bh_[q]);
                ldsm4(bB + q * 1024 + co + BTILE, bl_[q]);
            }
            mma_pass<MI, NJ>(acc, ah_, bh_);
            mma_pass<MI, NJ>(acc, al_, bh_);
            mma_pass<MI, NJ>(acc, ah_, bl_);
        }

        int tn = t + STG - 1;
        if (tn < KT) issue(tn, tn % STG);
        CP_COMMIT();
    }

    int mrow = m0 + wm * WTM + (lane >> 2);
    int ncol = n0 + wn * WTN + (lane & 3) * 2;
    #pragma unroll
    for (int mi = 0; mi < MI; mi++) {
        int r0 = mrow + mi * 16;
        #pragma unroll
        for (int nj = 0; nj < NJ; nj++) {
            int cb = ncol + nj * 8;
            #pragma unroll
            for (int half = 0; half < 2; half++) {
                int r = r0 + half * 8;
                size_t rowoff = (size_t)r * N;
                #pragma unroll
                for (int e = 0; e < 2; e++) {
                    int n = cb + e;
                    if (n < N) {
                        float v = acc[mi][nj][half * 2 + e];
                        if (bias) v += bias[n];
                        if (flags & FLAG_GELU)
                            v = 0.5f * v * (1.f + erff(v * 0.70710678118654752f));
                        if (Chi) {
                            split_store(v, Chi, Clo, rowoff + n);
                        } else {
                            if (flags & FLAG_ACCUM) v += Cf[rowoff + n];
                            Cf[rowoff + n] = v;
                        }
                    }
                }
            }
        }
    }
}

#define SMEM_BIG   (3 * 2 * (128 * 64 + 128 * 64))
#define SMEM_SMALL (4 * 2 * (64 * 64 + 128 * 64))

// ---------------- attention: 8 q per block (R14/R9 version) ----------------
#define QT 8
#define KTL 64
#define ATT_SMEM (QT*64*4 + QT*T*4 + 3*KTL*256 + 64)   // 84032

__global__ void __launch_bounds__(256, 2)
attention8(const float* __restrict__ qkv,
           __nv_bfloat16* __restrict__ ohi,
           __nv_bfloat16* __restrict__ olo)
{
    extern __shared__ char smem[];
    float* qs   = (float*)smem;
    float* sc   = qs + QT * 64;
    char*  kvb  = (char*)(sc + QT * T);
    float* invs = (float*)(kvb + 3 * KTL * 256);
    uint32_t kv0 = smem_u32(kvb);

    int qt = blockIdx.x, bh = blockIdx.y;
    int b = bh / H, h = bh % H;
    int q0 = qt * QT;
    int tid = threadIdx.x, lane = tid & 31, wid = tid >> 5;
    const float* base = qkv + (size_t)b * T * D3;

    for (int i = tid; i < QT * 64; i += 256) {
        int qq = i >> 6, d = i & 63;
        qs[i] = base[(size_t)(q0 + qq) * D3 + h * HD + d] * 0.125f;
    }

    int nkmax = q0 + QT;
    int ntile = (nkmax + KTL - 1) / KTL;

    auto issueKV = [&](int t, int s, int off) {
        #pragma unroll
        for (int j = 0; j < 4; j++) {
            int id = tid + j * 256;
            int r = id >> 4, ch = id & 15;
            uint32_t dst = kv0 + s * 16384 + r * 256 + ((ch ^ (r & 7)) << 4);
            const void* src = base + (size_t)(t * KTL + r) * D3 + off + h * HD + ch * 4;
            asm volatile("cp.async.cg.shared.global [%0], [%1], 16;" :: "r"(dst), "l"(src));
        }
    };

    // ---- phase 1: scores ----
    if (0 < ntile) issueKV(0, 0, D);
    CP_COMMIT();
    if (1 < ntile) issueKV(1, 1, D);
    CP_COMMIT();

    int kh = wid >> 2;
    int qp = (wid & 3) * 2;
    for (int t = 0; t < ntile; t++) {
        CP_WAIT(1);
        __syncthreads();
        int r = kh * 32 + lane;
        char* rowp = kvb + (t % 3) * 16384 + r * 256;
        int rsw = r & 7;
        float s0 = 0.f, s1 = 0.f;
        #pragma unroll
        for (int c = 0; c < 16; c++) {
            float4 kv4 = *(const float4*)(rowp + ((c ^ rsw) << 4));
            float4 a = *(const float4*)(qs + qp * 64 + c * 4);
            float4 bq = *(const float4*)(qs + (qp + 1) * 64 + c * 4);
            s0 = fmaf(a.x, kv4.x, s0); s0 = fmaf(a.y, kv4.y, s0);
            s0 = fmaf(a.z, kv4.z, s0); s0 = fmaf(a.w, kv4.w, s0);
            s1 = fmaf(bq.x, kv4.x, s1); s1 = fmaf(bq.y, kv4.y, s1);
            s1 = fmaf(bq.z, kv4.z, s1); s1 = fmaf(bq.w, kv4.w, s1);
        }
        sc[qp * T + t * KTL + r] = s0;
        sc[(qp + 1) * T + t * KTL + r] = s1;

        int tn = t + 2;
        if (tn < ntile) issueKV(tn, tn % 3, D);
        CP_COMMIT();
    }
    __syncthreads();

    // ---- phase 2: softmax ----
    {
        int w = wid;
        int nk = q0 + w + 1;
        float* row = sc + w * T;
        float m = -1e30f;
        for (int k = lane; k < nk; k += 32) m = fmaxf(m, row[k]);
        #pragma unroll
        for (int o = 16; o; o >>= 1) m = fmaxf(m, __shfl_xor_sync(0xFFFFFFFFu, m, o));
        float sum = 0.f;
        for (int k = lane; k < nk; k += 32) {
            float e = __expf(row[k] - m);
            row[k] = e;
            sum += e;
        }
        #pragma unroll
        for (int o = 16; o; o >>= 1) sum += __shfl_xor_sync(0xFFFFFFFFu, sum, o);
        for (int k = nk + lane; k < ntile * KTL; k += 32) row[k] = 0.f;
        if (lane == 0) invs[w] = 1.f / sum;
    }
    __syncthreads();

    // ---- phase 3: PV ----
    if (0 < ntile) issueKV(0, 0, 2 * D);
    CP_COMMIT();
    if (1 < ntile) issueKV(1, 1, 2 * D);
    CP_COMMIT();

    int d = tid & 63, g = tid >> 6;
    float acc0 = 0.f, acc1 = 0.f;
    int c = d >> 2, e4 = (d & 3) * 4;
    for (int t = 0; t < ntile; t++) {
        CP_WAIT(1);
        __syncthreads();
        const float* p0 = sc + g * T + t * KTL;
        const float* p1 = sc + (g + 4) * T + t * KTL;
        char* tb = kvb + (t % 3) * 16384;
        #pragma unroll 8
        for (int r = 0; r < KTL; r++) {
            float v = *(const float*)(tb + r * 256 + ((c ^ (r & 7)) << 4) + e4);
            acc0 = fmaf(p0[r], v, acc0);
            acc1 = fmaf(p1[r], v, acc1);
        }
        int tn = t + 2;
        if (tn < ntile) issueKV(tn, tn % 3, 2 * D);
        CP_COMMIT();
    }

    split_store(acc0 * invs[g],     ohi, olo, (size_t)(b * T + q0 + g)     * D + h * HD + d);
    split_store(acc1 * invs[g + 4], ohi, olo, (size_t)(b * T + q0 + g + 4) * D + h * HD + d);
}

// ---------------- host side ----------------
static inline void run_gemm_big(const __nv_bfloat16* Ahi, const __nv_bfloat16* Alo,
                                const __nv_bfloat16* Bhi, const __nv_bfloat16* Blo,
                                const float* bias, float* Cf,
                                __nv_bfloat16* Chi, __nv_bfloat16* Clo,
                                int N, int K, int flags)
{
    dim3 grid(M / 128, N / 128);
    gemm3x<128, 128, 4, 2, 3, false><<<grid, 256, SMEM_BIG>>>(Ahi, Alo, Bhi, Blo, bias, Cf, Chi, Clo, N, K, K, 0, flags);
}
static inline void run_gemm_lmhead(const __nv_bfloat16* Ahi, const __nv_bfloat16* Alo,
                                   const __nv_bfloat16* Bhi, const __nv_bfloat16* Blo,
                                   float* Cf, int N, int K)
{
    int nfull = (N / 128) * 128;
    dim3 grid(M / 128, nfull / 128);
    gemm3x<128, 128, 4, 2, 3, false><<<grid, 256, SMEM_BIG>>>(Ahi, Alo, Bhi, Blo, nullptr, Cf,
                                                              nullptr, nullptr, N, K, K, 0, 0);
    dim3 gridr(M / 128, 1);
    gemm3x<128, 128, 4, 2, 3, true><<<gridr, 256, SMEM_BIG>>>(Ahi, Alo, Bhi, Blo, nullptr, Cf,
                                                              nullptr, nullptr, N, K, K, nfull, 0);
}
// split-K x2 (no reduction kernel — fused add_ln follows)
static inline void run_gemm_splitk(const __nv_bfloat16* Ahi, const __nv_bfloat16* Alo,
                                   const __nv_bfloat16* Bhi, const __nv_bfloat16* Blo,
                                   float* partial, int K)
{
    dim3 grid(M / 64, D / 128, 2);
    gemm3x<64, 128, 2, 4, 4, false><<<grid, 256, SMEM_SMALL>>>(Ahi, Alo, Bhi, Blo, nullptr, partial,
                                                               nullptr, nullptr, D, K / 2, K, 0, 0);
}
static inline void run_split(const float* X, __nv_bfloat16* hi, __nv_bfloat16* lo, size_t n)
{
    int n4 = (int)(n / 4);
    split_kernel<<<(n4 + 255) / 256, 256>>>(X, hi, lo, n4);
}
static inline void run_wsplit(const float* W, __nv_bfloat16* hi, __nv_bfloat16* lo, int K, int N)
{
    dim3 grid(N / 32, K / 32);
    wsplit_t_kernel<<<grid, dim3(32, 8)>>>(W, hi, lo, K, N);
}

extern "C" void kernel_launch(void* const* d_in, const int* in_sizes, int n_in,
                              void* d_out, int out_size)
{
    const int*   ids    = (const int*)  d_in[0];
    const float* wte    = (const float*)d_in[1];
    const float* wpe    = (const float*)d_in[2];
    const float* ln1_g  = (const float*)d_in[3];
    const float* ln1_b  = (const float*)d_in[4];
    const float* attn_w = (const float*)d_in[5];
    const float* attn_b = (const float*)d_in[6];
    const float* proj_w = (const float*)d_in[7];
    const float* proj_b = (const float*)d_in[8];
    const float* ln2_g  = (const float*)d_in[9];
    const float* ln2_b  = (const float*)d_in[10];
    const float* fc_w   = (const float*)d_in[11];
    const float* fc_b   = (const float*)d_in[12];
    const float* out_w  = (const float*)d_in[13];
    const float* out_b  = (const float*)d_in[14];
    const float* lnf_g  = (const float*)d_in[15];
    const float* lnf_b  = (const float*)d_in[16];
    float* logits = (float*)d_out;

    cudaFuncSetAttribute((const void*)gemm3x<128, 128, 4, 2, 3, false>, cudaFuncAttributeMaxDynamicSharedMemorySize, SMEM_BIG);
    cudaFuncSetAttribute((const void*)gemm3x<128, 128, 4, 2, 3, true>,  cudaFuncAttributeMaxDynamicSharedMemorySize, SMEM_BIG);
    cudaFuncSetAttribute((const void*)gemm3x<64, 128, 2, 4, 4, false>,  cudaFuncAttributeMaxDynamicSharedMemorySize, SMEM_SMALL);
    cudaFuncSetAttribute((const void*)attention8, cudaFuncAttributeMaxDynamicSharedMemorySize, ATT_SMEM);

    float *x, *qkv;
    __nv_bfloat16 *ahi, *alo, *bhi, *blo, *whi, *wlo;
    cudaGetSymbolAddress((void**)&x,    g_x);
    cudaGetSymbolAddress((void**)&qkv,  g_qkv);
    cudaGetSymbolAddress((void**)&ahi,  g_ahi);
    cudaGetSymbolAddress((void**)&alo,  g_alo);
    cudaGetSymbolAddress((void**)&bhi,  g_bhi);
    cudaGetSymbolAddress((void**)&blo,  g_blo);
    cudaGetSymbolAddress((void**)&whi,  g_whi);
    cudaGetSymbolAddress((void**)&wlo,  g_wlo);

    embed_kernel<<<M, 256>>>(ids, wte, wpe);

    for (int l = 0; l < LAYERS; l++) {
        const float* aw = attn_w + (size_t)l * D * D3;
        const float* ab = attn_b + (size_t)l * D3;
        const float* pw = proj_w + (size_t)l * D * D;
        const float* pb = proj_b + (size_t)l * D;
        const float* fw = fc_w   + (size_t)l * D * D4;
        const float* fb = fc_b   + (size_t)l * D4;
        const float* ow = out_w  + (size_t)l * D4 * D;
        const float* ob = out_b  + (size_t)l * D;

        // attention block
        if (l == 0)
            ln_split_kernel<<<M, 256>>>(x, ln1_g, ln1_b, ahi, alo);
        run_wsplit(aw, whi, wlo, D, D3);
        run_gemm_big(ahi, alo, whi, wlo, ab, qkv, nullptr, nullptr, D3, D, 0);
        {
            dim3 grid(T / QT, B * H);
            attention8<<<grid, 256, ATT_SMEM>>>(qkv, ahi, alo);
        }
        run_wsplit(pw, whi, wlo, D, D);
        run_gemm_splitk(ahi, alo, whi, wlo, qkv, D);
        add_ln_split_kernel<<<M, 256>>>(x, qkv, pb,
                                        ln2_g + (size_t)l * D, ln2_b + (size_t)l * D, ahi, alo);

        // mlp block
        run_wsplit(fw, whi, wlo, D, D4);
        run_gemm_big(ahi, alo, whi, wlo, fb, nullptr, bhi, blo, D4, D, FLAG_GELU);
        run_wsplit(ow, whi, wlo, D4, D);
        run_gemm_splitk(bhi, blo, whi, wlo, qkv, D4);
        const float* ng = (l + 1 < LAYERS) ? ln1_g + (size_t)(l + 1) * D : lnf_g;
        const float* nb = (l + 1 < LAYERS) ? ln1_b + (size_t)(l + 1) * D : lnf_b;
        add_ln_split_kernel<<<M, 256>>>(x, qkv, ob, ng, nb, ahi, alo);
    }

    // tied lm_head (ahi/alo already hold lnf output)
    run_split(wte, whi, wlo, (size_t)V * D);
    run_gemm_lmhead(ahi, alo, whi, wlo, logits, V, D);
}

// round 17
// speedup vs baseline: 1.0330x; 1.0063x over previous
#include <cuda_runtime.h>
#include <cuda_bf16.h>
#include <math.h>
#include <stdint.h>

// ---------------- problem constants ----------------
#define LAYERS 4
#define D 768
#define H 12
#define HD 64
#define V 50257
#define B 2
#define T 1024
#define M (B*T)
#define D3 (3*D)
#define D4 (4*D)
#define EPS 1e-5f

#define FLAG_GELU  1
#define FLAG_ACCUM 2

// per-layer weight-split buffer offsets
#define LW_AW 0
#define LW_PW (D*D3)
#define LW_FW (LW_PW + D*D)
#define LW_OW (LW_FW + D*D4)
#define LW_TOT (LW_OW + D4*D)     // 7,077,888 elems per layer

// ---------------- scratch ----------------
__device__ float g_x   [(size_t)M * D];
__device__ float g_qkv [(size_t)M * D3];   // also split-K partial buffer (2*M*D floats)
__device__ __nv_bfloat16 g_ahi[(size_t)M * D4];
__device__ __nv_bfloat16 g_alo[(size_t)M * D4];
__device__ __nv_bfloat16 g_bhi[(size_t)M * D4];
__device__ __nv_bfloat16 g_blo[(size_t)M * D4];
__device__ __nv_bfloat16 g_whi[(size_t)V * D];                  // wte split
__device__ __nv_bfloat16 g_wlo[(size_t)V * D];
__device__ __nv_bfloat16 g_lwhi[(size_t)LAYERS * LW_TOT];       // layer weight splits
__device__ __nv_bfloat16 g_lwlo[(size_t)LAYERS * LW_TOT];

__device__ __forceinline__ uint32_t smem_u32(const void* p) {
    uint32_t a;
    asm("{ .reg .u64 t; cvta.to.shared.u64 t, %1; cvt.u32.u64 %0, t; }" : "=r"(a) : "l"(p));
    return a;
}
__device__ __forceinline__ void split_store(float v, __nv_bfloat16* hi, __nv_bfloat16* lo, size_t idx) {
    __nv_bfloat16 h = __float2bfloat16(v);
    hi[idx] = h;
    lo[idx] = __float2bfloat16(v - __bfloat162float(h));
}
#define CP_COMMIT() asm volatile("cp.async.commit_group;" ::: "memory")
#define CP_WAIT(n)  asm volatile("cp.async.wait_group %0;" :: "n"(n) : "memory")

// ---------------- embedding ----------------
__global__ void embed_kernel(const int* __restrict__ ids,
                             const float* __restrict__ wte,
                             const float* __restrict__ wpe)
{
    int row = blockIdx.x;
    int t   = row % T;
    int id  = ids[row];
    const float* we = wte + (size_t)id * D;
    const float* pe = wpe + (size_t)t  * D;
    float* out = g_x + (size_t)row * D;
    for (int i = threadIdx.x; i < D; i += blockDim.x)
        out[i] = we[i] + pe[i];
}

// ---------------- layernorm -> bf16 hi/lo (single-pass) ----------------
__device__ __forceinline__ void ln_core(float v0, float v1, float v2,
                                        int tid, int lane, int wid,
                                        const float* __restrict__ g,
                                        const float* __restrict__ b,
                                        __nv_bfloat16* __restrict__ ohi,
                                        __nv_bfloat16* __restrict__ olo,
                                        size_t base)
{
    float s  = v0 + v1 + v2;
    float s2 = v0 * v0 + v1 * v1 + v2 * v2;
    #pragma unroll
    for (int o = 16; o; o >>= 1) {
        s  += __shfl_xor_sync(0xFFFFFFFFu, s,  o);
        s2 += __shfl_xor_sync(0xFFFFFFFFu, s2, o);
    }
    __shared__ float ws[8], ws2[8];
    if (lane == 0) { ws[wid] = s; ws2[wid] = s2; }
    __syncthreads();
    s = 0.f; s2 = 0.f;
    #pragma unroll
    for (int i = 0; i < 8; i++) { s += ws[i]; s2 += ws2[i]; }
    float mu   = s * (1.f / (float)D);
    float var  = s2 * (1.f / (float)D) - mu * mu;
    float rstd = rsqrtf(var + EPS);

    split_store(g[tid]       * (v0 - mu) * rstd + b[tid],       ohi, olo, base + tid);
    split_store(g[tid + 256] * (v1 - mu) * rstd + b[tid + 256], ohi, olo, base + tid + 256);
    split_store(g[tid + 512] * (v2 - mu) * rstd + b[tid + 512], ohi, olo, base + tid + 512);
}

__global__ void ln_split_kernel(const float* __restrict__ x,
                                const float* __restrict__ g,
                                const float* __restrict__ b,
                                __nv_bfloat16* __restrict__ ohi,
                                __nv_bfloat16* __restrict__ olo)
{
    int row = blockIdx.x, tid = threadIdx.x;
    int lane = tid & 31, wid = tid >> 5;
    const float* xr = x + (size_t)row * D;
    float v0 = xr[tid], v1 = xr[tid + 256], v2 = xr[tid + 512];
    ln_core(v0, v1, v2, tid, lane, wid, g, b, ohi, olo, (size_t)row * D);
}

// ---------------- fused: x += p0+p1+bias, then LN -> bf16 hi/lo ----------------
__global__ void add_ln_split_kernel(float* __restrict__ x, const float* __restrict__ p,
                                    const float* __restrict__ bias,
                                    const float* __restrict__ g,
                                    const float* __restrict__ b,
                                    __nv_bfloat16* __restrict__ ohi,
                                    __nv_bfloat16* __restrict__ olo)
{
    int row = blockIdx.x, tid = threadIdx.x;
    int lane = tid & 31, wid = tid >> 5;
    size_t base = (size_t)row * D;
    const float* p1 = p + (size_t)M * D;
    float v0 = x[base + tid]       + p[base + tid]       + p1[base + tid]       + bias[tid];
    float v1 = x[base + tid + 256] + p[base + tid + 256] + p1[base + tid + 256] + bias[tid + 256];
    float v2 = x[base + tid + 512] + p[base + tid + 512] + p1[base + tid + 512] + bias[tid + 512];
    x[base + tid]       = v0;
    x[base + tid + 256] = v1;
    x[base + tid + 512] = v2;
    ln_core(v0, v1, v2, tid, lane, wid, g, b, ohi, olo, base);
}

// ---------------- fp32 -> bf16 hi/lo split (wte) ----------------
__global__ void split_kernel(const float* __restrict__ X,
                             __nv_bfloat16* __restrict__ hi,
                             __nv_bfloat16* __restrict__ lo, int n4)
{
    int i = blockIdx.x * blockDim.x + threadIdx.x;
    if (i >= n4) return;
    float4 v = ((const float4*)X)[i];
    float f[4] = {v.x, v.y, v.z, v.w};
    __nv_bfloat16 h[4], l[4];
    #pragma unroll
    for (int j = 0; j < 4; j++) {
        h[j] = __float2bfloat16(f[j]);
        l[j] = __float2bfloat16(f[j] - __bfloat162float(h[j]));
    }
    *(uint2*)(hi + 4 * (size_t)i) = *(uint2*)h;
    *(uint2*)(lo + 4 * (size_t)i) = *(uint2*)l;
}

// ---------------- W[K,N] -> hi/lo[N,K] transpose + split ----------------
__global__ void wsplit_t_kernel(const float* __restrict__ W,
                                __nv_bfloat16* __restrict__ hi,
                                __nv_bfloat16* __restrict__ lo, int K, int N)
{
    __shared__ float tb[32][33];
    int n0 = blockIdx.x * 32, k0 = blockIdx.y * 32;
    int tx = threadIdx.x, ty = threadIdx.y;
    #pragma unroll
    for (int i = 0; i < 4; i++)
        tb[ty + i * 8][tx] = W[(size_t)(k0 + ty + i * 8) * N + n0 + tx];
    __syncthreads();
    #pragma unroll
    for (int i = 0; i < 4; i++) {
        int n = n0 + ty + i * 8, k = k0 + tx;
        float v = tb[tx][ty + i * 8];
        __nv_bfloat16 h = __float2bfloat16(v);
        hi[(size_t)n * K + k] = h;
        lo[(size_t)n * K + k] = __float2bfloat16(v - __bfloat162float(h));
    }
}

// ---------------- mma helpers ----------------
__device__ __forceinline__ void ldsm4(uint32_t addr, uint32_t (&r)[4]) {
    asm volatile("ldmatrix.sync.aligned.m8n8.x4.shared.b16 {%0,%1,%2,%3}, [%4];"
        : "=r"(r[0]), "=r"(r[1]), "=r"(r[2]), "=r"(r[3]) : "r"(addr));
}

template<int MI, int NJ>
__device__ __forceinline__ void mma_pass(float (&acc)[MI][NJ][4],
                                         uint32_t (&a)[MI][4],
                                         uint32_t (&b)[NJ/2][4])
{
    #pragma unroll
    for (int mi = 0; mi < MI; mi++) {
        #pragma unroll
        for (int nj = 0; nj < NJ; nj++) {
            int q = nj >> 1, odd = nj & 1;
            uint32_t b0 = odd ? b[q][1] : b[q][0];
            uint32_t b1 = odd ? b[q][3] : b[q][2];
            asm volatile(
                "mma.sync.aligned.m16n8k16.row.col.f32.bf16.bf16.f32 "
                "{%0,%1,%2,%3}, {%4,%5,%6,%7}, {%8,%9}, {%0,%1,%2,%3};"
                : "+f"(acc[mi][nj][0]), "+f"(acc[mi][nj][1]),
                  "+f"(acc[mi][nj][2]), "+f"(acc[mi][nj][3])
                : "r"(a[mi][0]), "r"(a[mi][1]), "r"(a[mi][2]), "r"(a[mi][3]),
                  "r"(b0), "r"(b1));
        }
    }
}

// ---------------- GEMM (FROZEN R9 mainloop) ----------------
template<int BM, int BN, int WGM, int WGN, int STG, bool GUARD>
__global__ void __launch_bounds__(256, 2)
gemm3x(const __nv_bfloat16* __restrict__ Ahi, const __nv_bfloat16* __restrict__ Alo,
       const __nv_bfloat16* __restrict__ Bhi, const __nv_bfloat16* __restrict__ Blo,
       const float* __restrict__ bias, float* __restrict__ Cf,
       __nv_bfloat16* __restrict__ Chi, __nv_bfloat16* __restrict__ Clo,
       int N, int K, int ldk, int nbase, int flags)
{
    constexpr int WTM = BM / WGM, WTN = BN / WGN;
    constexpr int MI = WTM / 16, NJ = WTN / 8;
    constexpr int ATILE = BM * 64, BTILE = BN * 64;
    constexpr int STAGE = 2 * (ATILE + BTILE);
    constexpr int ACH = BM * 8, BCH = BN * 8;
    constexpr int PER = (ACH + BCH) / 256;

    {
        int zo = blockIdx.z * K;
        Ahi += zo; Alo += zo; Bhi += zo; Blo += zo;
        Cf  += (size_t)blockIdx.z * ((size_t)M * N);
    }

    extern __shared__ char smem[];
    const uint32_t sb = smem_u32(smem);
    const int tid = threadIdx.x, lane = tid & 31, wid = tid >> 5;
    const int wm = wid % WGM, wn = wid / WGM;
    const int m0 = blockIdx.x * BM, n0 = nbase + blockIdx.y * BN;
    const int KT = K / 32;

    float acc[MI][NJ][4] = {};

    auto issue = [&](int t, int s) {
        int kb = t * 32;
        uint32_t sbase = sb + s * STAGE;
        #pragma unroll
        for (int j = 0; j < PER; j++) {
            int id = tid + 256 * j;
            if (id < ACH) {
                int half = (id >= ACH / 2) ? 1 : 0;
                int r  = (id - half * (ACH / 2)) >> 2;
                int ch = id & 3;
                uint32_t dst = sbase + half * ATILE + r * 64 + ((ch ^ ((r >> 1) & 3)) << 4);
                const void* src = (half ? Alo : Ahi) + (size_t)(m0 + r) * ldk + kb + ch * 8;
                asm volatile("cp.async.cg.shared.global [%0], [%1], 16;" :: "r"(dst), "l"(src));
            } else {
                int id2 = id - ACH;
                int half = (id2 >= BCH / 2) ? 1 : 0;
                int r  = (id2 - half * (BCH / 2)) >> 2;
                int ch = id2 & 3;
                int bn = n0 + r;
                uint32_t dst = sbase + 2 * ATILE + half * BTILE + r * 64 + ((ch ^ ((r >> 1) & 3)) << 4);
                if (GUARD) {
                    const void* src = (half ? Blo : Bhi) + (size_t)(bn < N ? bn : 0) * ldk + kb + ch * 8;
                    int sz = (bn < N) ? 16 : 0;
                    asm volatile("cp.async.cg.shared.global [%0], [%1], 16, %2;" :: "r"(dst), "l"(src), "r"(sz));
                } else {
                    const void* src = (half ? Blo : Bhi) + (size_t)bn * ldk + kb + ch * 8;
                    asm volatile("cp.async.cg.shared.global [%0], [%1], 16;" :: "r"(dst), "l"(src));
                }
            }
        }
    };

    #pragma unroll
    for (int p = 0; p < STG - 1; p++) {
        if (p < KT) issue(p, p);
        CP_COMMIT();
    }

    const int lrow = lane & 15;
    const int lh   = lane >> 4;
    const int sw   = (lrow >> 1) & 3;

    for (int t = 0; t < KT; t++) {
        CP_WAIT(STG - 2);
        __syncthreads();

        uint32_t base = sb + (t % STG) * STAGE;
        uint32_t aB = base + (wm * WTM + lrow) * 64;
        uint32_t bB = base + 2 * ATILE + (wn * WTN + lrow) * 64;

        #pragma unroll
        for (int kk = 0; kk < 2; kk++) {
            uint32_t co = (uint32_t)(((kk * 2 + lh) ^ sw) << 4);
            uint32_t ah_[MI][4], al_[MI][4], bh_[NJ / 2][4], bl_[NJ / 2][4];
            #pragma unroll
            for (int mi = 0; mi < MI; mi++) {
                ldsm4(aB + mi * 1024 + co, ah_[mi]);
                ldsm4(aB + mi * 1024 + co + ATILE, al_[mi]);
            }
            #pragma unroll
            for (int q = 0; q < NJ / 2; q++) {
                ldsm4(bB + q * 1024 + co, bh_[q]);
                ldsm4(bB + q * 1024 + co + BTILE, bl_[q]);
            }
            mma_pass<MI, NJ>(acc, ah_, bh_);
            mma_pass<MI, NJ>(acc, al_, bh_);
            mma_pass<MI, NJ>(acc, ah_, bl_);
        }

        int tn = t + STG - 1;
        if (tn < KT) issue(tn, tn % STG);
        CP_COMMIT();
    }

    int mrow = m0 + wm * WTM + (lane >> 2);
    int ncol = n0 + wn * WTN + (lane & 3) * 2;
    #pragma unroll
    for (int mi = 0; mi < MI; mi++) {
        int r0 = mrow + mi * 16;
        #pragma unroll
        for (int nj = 0; nj < NJ; nj++) {
            int cb = ncol + nj * 8;
            #pragma unroll
            for (int half = 0; half < 2; half++) {
                int r = r0 + half * 8;
                size_t rowoff = (size_t)r * N;
                #pragma unroll
                for (int e = 0; e < 2; e++) {
                    int n = cb + e;
                    if (n < N) {
                        float v = acc[mi][nj][half * 2 + e];
                        if (bias) v += bias[n];
                        if (flags & FLAG_GELU)
                            v = 0.5f * v * (1.f + erff(v * 0.70710678118654752f));
                        if (Chi) {
                            split_store(v, Chi, Clo, rowoff + n);
                        } else {
                            if (flags & FLAG_ACCUM) v += Cf[rowoff + n];
                            Cf[rowoff + n] = v;
                        }
                    }
                }
            }
        }
    }
}

#define SMEM_BIG   (3 * 2 * (128 * 64 + 128 * 64))
#define SMEM_SMALL (4 * 2 * (64 * 64 + 128 * 64))

// ---------------- attention: 8 q per block (R14/R9 version) ----------------
#define QT 8
#define KTL 64
#define ATT_SMEM (QT*64*4 + QT*T*4 + 3*KTL*256 + 64)   // 84032

__global__ void __launch_bounds__(256, 2)
attention8(const float* __restrict__ qkv,
           __nv_bfloat16* __restrict__ ohi,
           __nv_bfloat16* __restrict__ olo)
{
    extern __shared__ char smem[];
    float* qs   = (float*)smem;
    float* sc   = qs + QT * 64;
    char*  kvb  = (char*)(sc + QT * T);
    float* invs = (float*)(kvb + 3 * KTL * 256);
    uint32_t kv0 = smem_u32(kvb);

    int qt = blockIdx.x, bh = blockIdx.y;
    int b = bh / H, h = bh % H;
    int q0 = qt * QT;
    int tid = threadIdx.x, lane = tid & 31, wid = tid >> 5;
    const float* base = qkv + (size_t)b * T * D3;

    for (int i = tid; i < QT * 64; i += 256) {
        int qq = i >> 6, d = i & 63;
        qs[i] = base[(size_t)(q0 + qq) * D3 + h * HD + d] * 0.125f;
    }

    int nkmax = q0 + QT;
    int ntile = (nkmax + KTL - 1) / KTL;

    auto issueKV = [&](int t, int s, int off) {
        #pragma unroll
        for (int j = 0; j < 4; j++) {
            int id = tid + j * 256;
            int r = id >> 4, ch = id & 15;
            uint32_t dst = kv0 + s * 16384 + r * 256 + ((ch ^ (r & 7)) << 4);
            const void* src = base + (size_t)(t * KTL + r) * D3 + off + h * HD + ch * 4;
            asm volatile("cp.async.cg.shared.global [%0], [%1], 16;" :: "r"(dst), "l"(src));
        }
    };

    // ---- phase 1: scores ----
    if (0 < ntile) issueKV(0, 0, D);
    CP_COMMIT();
    if (1 < ntile) issueKV(1, 1, D);
    CP_COMMIT();

    int kh = wid >> 2;
    int qp = (wid & 3) * 2;
    for (int t = 0; t < ntile; t++) {
        CP_WAIT(1);
        __syncthreads();
        int r = kh * 32 + lane;
        char* rowp = kvb + (t % 3) * 16384 + r * 256;
        int rsw = r & 7;
        float s0 = 0.f, s1 = 0.f;
        #pragma unroll
        for (int c = 0; c < 16; c++) {
            float4 kv4 = *(const float4*)(rowp + ((c ^ rsw) << 4));
            float4 a = *(const float4*)(qs + qp * 64 + c * 4);
            float4 bq = *(const float4*)(qs + (qp + 1) * 64 + c * 4);
            s0 = fmaf(a.x, kv4.x, s0); s0 = fmaf(a.y, kv4.y, s0);
            s0 = fmaf(a.z, kv4.z, s0); s0 = fmaf(a.w, kv4.w, s0);
            s1 = fmaf(bq.x, kv4.x, s1); s1 = fmaf(bq.y, kv4.y, s1);
            s1 = fmaf(bq.z, kv4.z, s1); s1 = fmaf(bq.w, kv4.w, s1);
        }
        sc[qp * T + t * KTL + r] = s0;
        sc[(qp + 1) * T + t * KTL + r] = s1;

        int tn = t + 2;
        if (tn < ntile) issueKV(tn, tn % 3, D);
        CP_COMMIT();
    }
    __syncthreads();

    // ---- phase 2: softmax ----
    {
        int w = wid;
        int nk = q0 + w + 1;
        float* row = sc + w * T;
        float m = -1e30f;
        for (int k = lane; k < nk; k += 32) m = fmaxf(m, row[k]);
        #pragma unroll
        for (int o = 16; o; o >>= 1) m = fmaxf(m, __shfl_xor_sync(0xFFFFFFFFu, m, o));
        float sum = 0.f;
        for (int k = lane; k < nk; k += 32) {
            float e = __expf(row[k] - m);
            row[k] = e;
            sum += e;
        }
        #pragma unroll
        for (int o = 16; o; o >>= 1) sum += __shfl_xor_sync(0xFFFFFFFFu, sum, o);
        for (int k = nk + lane; k < ntile * KTL; k += 32) row[k] = 0.f;
        if (lane == 0) invs[w] = 1.f / sum;
    }
    __syncthreads();

    // ---- phase 3: PV ----
    if (0 < ntile) issueKV(0, 0, 2 * D);
    CP_COMMIT();
    if (1 < ntile) issueKV(1, 1, 2 * D);
    CP_COMMIT();

    int d = tid & 63, g = tid >> 6;
    float acc0 = 0.f, acc1 = 0.f;
    int c = d >> 2, e4 = (d & 3) * 4;
    for (int t = 0; t < ntile; t++) {
        CP_WAIT(1);
        __syncthreads();
        const float* p0 = sc + g * T + t * KTL;
        const float* p1 = sc + (g + 4) * T + t * KTL;
        char* tb = kvb + (t % 3) * 16384;
        #pragma unroll 8
        for (int r = 0; r < KTL; r++) {
            float v = *(const float*)(tb + r * 256 + ((c ^ (r & 7)) << 4) + e4);
            acc0 = fmaf(p0[r], v, acc0);
            acc1 = fmaf(p1[r], v, acc1);
        }
        int tn = t + 2;
        if (tn < ntile) issueKV(tn, tn % 3, 2 * D);
        CP_COMMIT();
    }

    split_store(acc0 * invs[g],     ohi, olo, (size_t)(b * T + q0 + g)     * D + h * HD + d);
    split_store(acc1 * invs[g + 4], ohi, olo, (size_t)(b * T + q0 + g + 4) * D + h * HD + d);
}

// ---------------- host side ----------------
static inline void run_gemm_big(const __nv_bfloat16* Ahi, const __nv_bfloat16* Alo,
                                const __nv_bfloat16* Bhi, const __nv_bfloat16* Blo,
                                const float* bias, float* Cf,
                                __nv_bfloat16* Chi, __nv_bfloat16* Clo,
                                int N, int K, int flags)
{
    dim3 grid(M / 128, N / 128);
    gemm3x<128, 128, 4, 2, 3, false><<<grid, 256, SMEM_BIG>>>(Ahi, Alo, Bhi, Blo, bias, Cf, Chi, Clo, N, K, K, 0, flags);
}
static inline void run_gemm_lmhead(const __nv_bfloat16* Ahi, const __nv_bfloat16* Alo,
                                   const __nv_bfloat16* Bhi, const __nv_bfloat16* Blo,
                                   float* Cf, int N, int K)
{
    int nfull = (N / 128) * 128;
    dim3 grid(M / 128, nfull / 128);
    gemm3x<128, 128, 4, 2, 3, false><<<grid, 256, SMEM_BIG>>>(Ahi, Alo, Bhi, Blo, nullptr, Cf,
                                                              nullptr, nullptr, N, K, K, 0, 0);
    dim3 gridr(M / 128, 1);
    gemm3x<128, 128, 4, 2, 3, true><<<gridr, 256, SMEM_BIG>>>(Ahi, Alo, Bhi, Blo, nullptr, Cf,
                                                              nullptr, nullptr, N, K, K, nfull, 0);
}
static inline void run_gemm_splitk(const __nv_bfloat16* Ahi, const __nv_bfloat16* Alo,
                                   const __nv_bfloat16* Bhi, const __nv_bfloat16* Blo,
                                   float* partial, int K)
{
    dim3 grid(M / 64, D / 128, 2);
    gemm3x<64, 128, 2, 4, 4, false><<<grid, 256, SMEM_SMALL>>>(Ahi, Alo, Bhi, Blo, nullptr, partial,
                                                               nullptr, nullptr, D, K / 2, K, 0, 0);
}
static inline void run_split_s(const float* X, __nv_bfloat16* hi, __nv_bfloat16* lo, size_t n,
                               cudaStream_t st)
{
    int n4 = (int)(n / 4);
    split_kernel<<<(n4 + 255) / 256, 256, 0, st>>>(X, hi, lo, n4);
}
static inline void run_wsplit_s(const float* W, __nv_bfloat16* hi, __nv_bfloat16* lo, int K, int N,
                                cudaStream_t st)
{
    dim3 grid(N / 32, K / 32);
    wsplit_t_kernel<<<grid, dim3(32, 8), 0, st>>>(W, hi, lo, K, N);
}

// static side stream + events (created once on the first, uncaptured call;
// identical kernel work is issued on every call)
static cudaStream_t g_side = nullptr;
static cudaEvent_t  g_evroot = nullptr;
static cudaEvent_t  g_ev[17];

extern "C" void kernel_launch(void* const* d_in, const int* in_sizes, int n_in,
                              void* d_out, int out_size)
{
    const int*   ids    = (const int*)  d_in[0];
    const float* wte    = (const float*)d_in[1];
    const float* wpe    = (const float*)d_in[2];
    const float* ln1_g  = (const float*)d_in[3];
    const float* ln1_b  = (const float*)d_in[4];
    const float* attn_w = (const float*)d_in[5];
    const float* attn_b = (const float*)d_in[6];
    const float* proj_w = (const float*)d_in[7];
    const float* proj_b = (const float*)d_in[8];
    const float* ln2_g  = (const float*)d_in[9];
    const float* ln2_b  = (const float*)d_in[10];
    const float* fc_w   = (const float*)d_in[11];
    const float* fc_b   = (const float*)d_in[12];
    const float* out_w  = (const float*)d_in[13];
    const float* out_b  = (const float*)d_in[14];
    const float* lnf_g  = (const float*)d_in[15];
    const float* lnf_b  = (const float*)d_in[16];
    float* logits = (float*)d_out;

    if (!g_side) {
        cudaStreamCreateWithFlags(&g_side, cudaStreamNonBlocking);
        cudaEventCreateWithFlags(&g_evroot, cudaEventDisableTiming);
        for (int i = 0; i < 17; i++)
            cudaEventCreateWithFlags(&g_ev[i], cudaEventDisableTiming);
    }

    cudaFuncSetAttribute((const void*)gemm3x<128, 128, 4, 2, 3, false>, cudaFuncAttributeMaxDynamicSharedMemorySize, SMEM_BIG);
    cudaFuncSetAttribute((const void*)gemm3x<128, 128, 4, 2, 3, true>,  cudaFuncAttributeMaxDynamicSharedMemorySize, SMEM_BIG);
    cudaFuncSetAttribute((const void*)gemm3x<64, 128, 2, 4, 4, false>,  cudaFuncAttributeMaxDynamicSharedMemorySize, SMEM_SMALL);
    cudaFuncSetAttribute((const void*)attention8, cudaFuncAttributeMaxDynamicSharedMemorySize, ATT_SMEM);

    float *x, *qkv;
    __nv_bfloat16 *ahi, *alo, *bhi, *blo, *whi, *wlo, *lwhi, *lwlo;
    cudaGetSymbolAddress((void**)&x,    g_x);
    cudaGetSymbolAddress((void**)&qkv,  g_qkv);
    cudaGetSymbolAddress((void**)&ahi,  g_ahi);
    cudaGetSymbolAddress((void**)&alo,  g_alo);
    cudaGetSymbolAddress((void**)&bhi,  g_bhi);
    cudaGetSymbolAddress((void**)&blo,  g_blo);
    cudaGetSymbolAddress((void**)&whi,  g_whi);
    cudaGetSymbolAddress((void**)&wlo,  g_wlo);
    cudaGetSymbolAddress((void**)&lwhi, g_lwhi);
    cudaGetSymbolAddress((void**)&lwlo, g_lwlo);

    // ---- fork side stream: all weight splits, in consumption order ----
    cudaEventRecord(g_evroot, 0);
    cudaStreamWaitEvent(g_side, g_evroot, 0);
    for (int l = 0; l < LAYERS; l++) {
        size_t lo_ = (size_t)l * LW_TOT;
        run_wsplit_s(attn_w + (size_t)l * D * D3, lwhi + lo_ + LW_AW, lwlo + lo_ + LW_AW, D, D3, g_side);
        cudaEventRecord(g_ev[4 * l + 0], g_side);
        run_wsplit_s(proj_w + (size_t)l * D * D,  lwhi + lo_ + LW_PW, lwlo + lo_ + LW_PW, D, D,  g_side);
        cudaEventRecord(g_ev[4 * l + 1], g_side);
        run_wsplit_s(fc_w   + (size_t)l * D * D4, lwhi + lo_ + LW_FW, lwlo + lo_ + LW_FW, D, D4, g_side);
        cudaEventRecord(g_ev[4 * l + 2], g_side);
        run_wsplit_s(out_w  + (size_t)l * D4 * D, lwhi + lo_ + LW_OW, lwlo + lo_ + LW_OW, D4, D, g_side);
        cudaEventRecord(g_ev[4 * l + 3], g_side);
    }
    run_split_s(wte, whi, wlo, (size_t)V * D, g_side);
    cudaEventRecord(g_ev[16], g_side);

    // ---- main chain ----
    embed_kernel<<<M, 256>>>(ids, wte, wpe);

    for (int l = 0; l < LAYERS; l++) {
        size_t lo_ = (size_t)l * LW_TOT;
        const __nv_bfloat16* awh = lwhi + lo_ + LW_AW; const __nv_bfloat16* awl = lwlo + lo_ + LW_AW;
        const __nv_bfloat16* pwh = lwhi + lo_ + LW_PW; const __nv_bfloat16* pwl = lwlo + lo_ + LW_PW;
        const __nv_bfloat16* fwh = lwhi + lo_ + LW_FW; const __nv_bfloat16* fwl = lwlo + lo_ + LW_FW;
        const __nv_bfloat16* owh = lwhi + lo_ + LW_OW; const __nv_bfloat16* owl = lwlo + lo_ + LW_OW;
        const float* ab = attn_b + (size_t)l * D3;
        const float* pb = proj_b + (size_t)l * D;
        const float* fb = fc_b   + (size_t)l * D4;
        const float* ob = out_b  + (size_t)l * D;

        // attention block
        if (l == 0)
            ln_split_kernel<<<M, 256>>>(x, ln1_g, ln1_b, ahi, alo);
        cudaStreamWaitEvent(0, g_ev[4 * l + 0], 0);
        run_gemm_big(ahi, alo, awh, awl, ab, qkv, nullptr, nullptr, D3, D, 0);
        {
            dim3 grid(T / QT, B * H);
            attention8<<<grid, 256, ATT_SMEM>>>(qkv, ahi, alo);
        }
        cudaStreamWaitEvent(0, g_ev[4 * l + 1], 0);
        run_gemm_splitk(ahi, alo, pwh, pwl, qkv, D);
        add_ln_split_kernel<<<M, 256>>>(x, qkv, pb,
                                        ln2_g + (size_t)l * D, ln2_b + (size_t)l * D, ahi, alo);

        // mlp block
        cudaStreamWaitEvent(0, g_ev[4 * l + 2], 0);
        run_gemm_big(ahi, alo, fwh, fwl, fb, nullptr, bhi, blo, D4, D, FLAG_GELU);
        cudaStreamWaitEvent(0, g_ev[4 * l + 3], 0);
        run_gemm_splitk(bhi, blo, owh, owl, qkv, D4);
        const float* ng = (l + 1 < LAYERS) ? ln1_g + (size_t)(l + 1) * D : lnf_g;
        const float* nb = (l + 1 < LAYERS) ? ln1_b + (size_t)(l + 1) * D : lnf_b;
        add_ln_split_kernel<<<M, 256>>>(x, qkv, ob, ng, nb, ahi, alo);
    }

    // tied lm_head (ahi/alo already hold lnf output)
    cudaStreamWaitEvent(0, g_ev[16], 0);
    run_gemm_lmhead(ahi, alo, whi, wlo, logits, V, D);
}